// round 5
// baseline (speedup 1.0000x reference)
#include <cuda_runtime.h>
#include <stdint.h>

#define N_NODES 10242
#define NNZ_MAX 71694
#define BT      32          // B*T
#define C_IN    16
#define F       512         // C_IN * BT
#define KS      20
#define COUT    32
#define CK      (C_IN * KS)

typedef unsigned long long ull;

// ---------------- device scratch (no runtime allocation allowed) ----------------
__device__ float g_buf[(size_t)3 * N_NODES * F];   // rolling Chebyshev slices, ~63MB (L2-resident)
__device__ int   g_cnt[N_NODES];
__device__ int   g_rowptr[N_NODES + 1];
__device__ int   g_cursor[N_NODES];
__device__ int   g_colidx[NNZ_MAX];
__device__ float g_vals[NNZ_MAX];

// ---------------- CSR build (parallel, multi-kernel) ----------------
__global__ void zero_cnt_kernel() {
    int i = blockIdx.x * blockDim.x + threadIdx.x;
    if (i < N_NODES) g_cnt[i] = 0;
}

__global__ void csr_count_kernel(const int* __restrict__ erow, int nnz) {
    int e = blockIdx.x * blockDim.x + threadIdx.x;
    if (e < nnz) atomicAdd(&g_cnt[erow[e]], 1);
}

__global__ void csr_scan_kernel(int nnz) {
    __shared__ int sm[1024];
    int t = threadIdx.x;
    const int CH = 11;                       // 1024*11 = 11264 >= 10242
    int base = t * CH;
    int s = 0;
#pragma unroll
    for (int i = 0; i < CH; ++i) {
        int idx = base + i;
        if (idx < N_NODES) s += g_cnt[idx];
    }
    sm[t] = s;
    __syncthreads();
    for (int off = 1; off < 1024; off <<= 1) {
        int v = (t >= off) ? sm[t - off] : 0;
        __syncthreads();
        sm[t] += v;
        __syncthreads();
    }
    int run = sm[t] - s;                     // exclusive prefix at chunk start
#pragma unroll
    for (int i = 0; i < CH; ++i) {
        int idx = base + i;
        if (idx < N_NODES) {
            g_rowptr[idx] = run;
            g_cursor[idx] = run;
            run += g_cnt[idx];
        }
    }
    if (t == 0) g_rowptr[N_NODES] = nnz;
}

__global__ void csr_scatter_kernel(const int* __restrict__ erow,
                                   const int* __restrict__ ecol,
                                   const float* __restrict__ eval, int nnz) {
    int e = blockIdx.x * blockDim.x + threadIdx.x;
    if (e < nnz) {
        int r = erow[e];
        int p = atomicAdd(&g_cursor[r], 1);
        g_colidx[p] = ecol[e];
        g_vals[p]   = eval[e];
    }
}

// Canonical per-row order (col asc, then val asc) -> deterministic fp sums
__global__ void csr_sort_kernel() {
    int r = blockIdx.x * blockDim.x + threadIdx.x;
    if (r >= N_NODES) return;
    int s = g_rowptr[r], e = g_rowptr[r + 1];
    for (int i = s + 1; i < e; ++i) {
        int   kc = g_colidx[i];
        float kv = g_vals[i];
        int j = i - 1;
        while (j >= s && (g_colidx[j] > kc || (g_colidx[j] == kc && g_vals[j] > kv))) {
            g_colidx[j + 1] = g_colidx[j];
            g_vals[j + 1]   = g_vals[j];
            --j;
        }
        g_colidx[j + 1] = kc;
        g_vals[j + 1]   = kv;
    }
}

// ---------------- packed-f32x2 helpers ----------------
__device__ __forceinline__ void ffma2(ull& d, ull a, ull b) {
    asm("fma.rn.f32x2 %0, %1, %2, %0;" : "+l"(d) : "l"(a), "l"(b));
}
__device__ __forceinline__ ull dup2(float v) {
    ull r; asm("mov.b64 %0, {%1, %1};" : "=l"(r) : "f"(v)); return r;
}
__device__ __forceinline__ ull add2(ull a, ull b) {
    ull r; asm("add.rn.f32x2 %0, %1, %2;" : "=l"(r) : "l"(a), "l"(b)); return r;
}

// projection of this warp's slice row (in sx) into out; k's W slice in swk[c][cout]
// accumulate==0: store, else RMW.
__device__ __forceinline__ void project_row(const float* __restrict__ sxrow,
                                            const float (*swk)[COUT],
                                            float* __restrict__ out,
                                            int n, int lane, int accumulate) {
    int cj = lane & 7;                       // cout group: couts cj*4 .. cj*4+3
#pragma unroll
    for (int p = 0; p < 8; ++p) {
        int bt = p * 4 + (lane >> 3);
        ull a0 = 0ull, a1 = 0ull;
#pragma unroll
        for (int c = 0; c < C_IN; ++c) {
            ull s2 = dup2(sxrow[c * BT + bt]);
            float4 w4 = *(const float4*)&swk[c][cj * 4];
            ffma2(a0, s2, ((ull*)&w4)[0]);
            ffma2(a1, s2, ((ull*)&w4)[1]);
        }
        float* op = out + ((size_t)bt * N_NODES + n) * COUT + cj * 4;
        if (accumulate) {
            float4 prev = *(float4*)op;
            a0 = add2(a0, ((ull*)&prev)[0]);
            a1 = add2(a1, ((ull*)&prev)[1]);
        }
        float4 res;
        ((ull*)&res)[0] = a0;
        ((ull*)&res)[1] = a1;
        *(float4*)op = res;
    }
}

// load W slice k into smem: swk[c][cout] = W[cout*CK + c*KS + k]
__device__ __forceinline__ void load_wk(const float* __restrict__ W, int k,
                                        float (*swk)[COUT], int tid) {
#pragma unroll
    for (int e = tid; e < C_IN * COUT; e += 256) {
        int c    = e >> 5;
        int cout = e & 31;
        swk[c][cout] = __ldg(&W[cout * CK + c * KS + k]);
    }
}

// ---------------- step 0: transpose x into buf0 + project T0 into out ----------------
__global__ void __launch_bounds__(256) xpose_proj0_kernel(const float* __restrict__ x,
                                                          const float* __restrict__ W,
                                                          float* __restrict__ out) {
    __shared__ float sx[8][F];
    __shared__ float swk[C_IN][COUT];
    int tid  = threadIdx.x;
    int wid  = tid >> 5;
    int lane = tid & 31;
    load_wk(W, 0, swk, tid);
    __syncthreads();

    int n = blockIdx.x * 8 + wid;
    if (n >= N_NODES) return;

    // lane l loads x[bt=l, n, 0..15] (16 contiguous floats), stores sx[c*32+l]
    float4 v0 = __ldg((const float4*)&x[((size_t)lane * N_NODES + n) * C_IN]);
    float4 v1 = __ldg((const float4*)&x[((size_t)lane * N_NODES + n) * C_IN + 4]);
    float4 v2 = __ldg((const float4*)&x[((size_t)lane * N_NODES + n) * C_IN + 8]);
    float4 v3 = __ldg((const float4*)&x[((size_t)lane * N_NODES + n) * C_IN + 12]);
    const float* vv = (const float*)&v0;   // v0..v3 contiguous? not guaranteed; unroll explicitly
    float vals[16] = {v0.x, v0.y, v0.z, v0.w, v1.x, v1.y, v1.z, v1.w,
                      v2.x, v2.y, v2.z, v2.w, v3.x, v3.y, v3.z, v3.w};
    (void)vv;
#pragma unroll
    for (int c = 0; c < C_IN; ++c) sx[wid][c * BT + lane] = vals[c];
    __syncwarp();

    // write slice 0 to buf0 (coalesced via float4)
    float4* dst = (float4*)(g_buf + (size_t)n * F);
    const float4* srow = (const float4*)sx[wid];
    dst[lane] = srow[lane];
    dst[lane + 32] = srow[lane + 32];
    dst[lane + 64] = srow[lane + 64];
    dst[lane + 96] = srow[lane + 96];

    project_row(sx[wid], swk, out, n, lane, 0);   // store (initializes out)
}

// ---------------- fused SpMM + projection step ----------------
#define FMA4(A, V, U) do { \
    A.x = fmaf(V, U.x, A.x); A.y = fmaf(V, U.y, A.y); \
    A.z = fmaf(V, U.z, A.z); A.w = fmaf(V, U.w, A.w); } while (0)

__global__ void __launch_bounds__(256) spmm_fused_kernel(const float* __restrict__ W,
                                                         float* __restrict__ out,
                                                         int kc, int kp, int ko,
                                                         int k, int first) {
    __shared__ float sx[8][F];
    __shared__ float swk[C_IN][COUT];
    int tid  = threadIdx.x;
    int wid  = tid >> 5;
    int lane = tid & 31;
    load_wk(W, k, swk, tid);
    __syncthreads();

    int n = blockIdx.x * 8 + wid;
    if (n >= N_NODES) return;

    const float4* __restrict__ cur = (const float4*)(g_buf + (size_t)kc * N_NODES * F);
    int s = g_rowptr[n], e = g_rowptr[n + 1];

    float4 a0 = make_float4(0.f, 0.f, 0.f, 0.f), a1 = a0, a2 = a0, a3 = a0;

    int i = s;
    for (; i + 2 <= e; i += 2) {
        int   c0 = __ldg(&g_colidx[i]);
        int   c1 = __ldg(&g_colidx[i + 1]);
        float v0 = __ldg(&g_vals[i]);
        float v1 = __ldg(&g_vals[i + 1]);
        const float4* p0 = cur + (size_t)c0 * 128 + lane;
        const float4* p1 = cur + (size_t)c1 * 128 + lane;
        float4 u0 = __ldg(p0),      u1 = __ldg(p0 + 32),
               u2 = __ldg(p0 + 64), u3 = __ldg(p0 + 96);
        float4 w0 = __ldg(p1),      w1 = __ldg(p1 + 32),
               w2 = __ldg(p1 + 64), w3 = __ldg(p1 + 96);
        FMA4(a0, v0, u0); FMA4(a1, v0, u1); FMA4(a2, v0, u2); FMA4(a3, v0, u3);
        FMA4(a0, v1, w0); FMA4(a1, v1, w1); FMA4(a2, v1, w2); FMA4(a3, v1, w3);
    }
    if (i < e) {
        int   c0 = __ldg(&g_colidx[i]);
        float v0 = __ldg(&g_vals[i]);
        const float4* p0 = cur + (size_t)c0 * 128 + lane;
        float4 u0 = __ldg(p0),      u1 = __ldg(p0 + 32),
               u2 = __ldg(p0 + 64), u3 = __ldg(p0 + 96);
        FMA4(a0, v0, u0); FMA4(a1, v0, u1); FMA4(a2, v0, u2); FMA4(a3, v0, u3);
    }

    size_t o = (size_t)n * 128 + lane;
    float4* dst = (float4*)(g_buf + (size_t)ko * N_NODES * F);
    float4 r0, r1, r2, r3;
    if (first) {
        r0 = a0; r1 = a1; r2 = a2; r3 = a3;
    } else {
        const float4* __restrict__ prev = (const float4*)(g_buf + (size_t)kp * N_NODES * F);
        float4 p0 = prev[o], p1 = prev[o + 32], p2 = prev[o + 64], p3 = prev[o + 96];
        r0 = make_float4(2.f * a0.x - p0.x, 2.f * a0.y - p0.y, 2.f * a0.z - p0.z, 2.f * a0.w - p0.w);
        r1 = make_float4(2.f * a1.x - p1.x, 2.f * a1.y - p1.y, 2.f * a1.z - p1.z, 2.f * a1.w - p1.w);
        r2 = make_float4(2.f * a2.x - p2.x, 2.f * a2.y - p2.y, 2.f * a2.z - p2.z, 2.f * a2.w - p2.w);
        r3 = make_float4(2.f * a3.x - p3.x, 2.f * a3.y - p3.y, 2.f * a3.z - p3.z, 2.f * a3.w - p3.w);
    }
    dst[o] = r0; dst[o + 32] = r1; dst[o + 64] = r2; dst[o + 96] = r3;

    // stash the new slice row in smem for the projection
    float4* srow = (float4*)sx[wid];
    srow[lane] = r0; srow[lane + 32] = r1; srow[lane + 64] = r2; srow[lane + 96] = r3;
    __syncwarp();

    project_row(sx[wid], swk, out, n, lane, 1);   // accumulate
}

// ---------------- launch ----------------
extern "C" void kernel_launch(void* const* d_in, const int* in_sizes, int n_in,
                              void* d_out, int out_size) {
    const float* x    = (const float*)d_in[0];
    const int*   erow = (const int*)  d_in[1];
    const int*   ecol = (const int*)  d_in[2];
    const float* eval = (const float*)d_in[3];
    const float* W    = (const float*)d_in[4];
    float*       out  = (float*)d_out;
    int nnz = in_sizes[1];
    if (nnz > NNZ_MAX) nnz = NNZ_MAX;

    zero_cnt_kernel   <<<(N_NODES + 255) / 256, 256>>>();
    csr_count_kernel  <<<(nnz + 255) / 256, 256>>>(erow, nnz);
    csr_scan_kernel   <<<1, 1024>>>(nnz);
    csr_scatter_kernel<<<(nnz + 255) / 256, 256>>>(erow, ecol, eval, nnz);
    csr_sort_kernel   <<<(N_NODES + 127) / 128, 128>>>();

    const int BLKS = (N_NODES + 7) / 8;    // 8 nodes (warps) per block
    xpose_proj0_kernel<<<BLKS, 256>>>(x, W, out);          // slice 0 + proj0 (init out)

    // slice 1 = L x0 (buffers roll mod 3)
    spmm_fused_kernel<<<BLKS, 256>>>(W, out, 0, 0, 1, 1, 1);
    for (int k = 2; k < KS; ++k)
        spmm_fused_kernel<<<BLKS, 256>>>(W, out, (k - 1) % 3, (k - 2) % 3, k % 3, k, 0);
}